// round 1
// baseline (speedup 1.0000x reference)
#include <cuda_runtime.h>
#include <math.h>

// MusicRNN: 2-layer LSTM (B=2048, T=256, I=88, H=64) + FC (O=13).
// Strategy: batch-partitioned persistent-per-layer kernels. Each CTA owns a
// 16-element batch slice and runs the full T=256 recurrence with all weights
// resident in shared memory. No inter-CTA communication -> no grid syncs.
// Layer1 writes ys1 to a __device__ scratch; layer2 reads it and fuses the FC.

namespace {
constexpr int B  = 2048;
constexpr int T  = 256;
constexpr int I  = 88;
constexpr int H  = 64;
constexpr int O  = 13;
constexpr int G4 = 4 * H;   // 256 gate columns
constexpr int BS = 16;      // batch elements per CTA
constexpr int BSP = 20;     // padded batch stride in sXH (bank-conflict pad)
constexpr int PJ = 260;     // padded gate stride (multiple of 4, not of 32)
}

// ys1 scratch: [T][B][H] fp32 = 128 MB (static device array: allocation-free rule)
__device__ float g_ys1[(size_t)T * B * H];

typedef unsigned long long ull;

__device__ __forceinline__ ull pack2(float a, float b) {
    ull r; asm("mov.b64 %0, {%1, %2};" : "=l"(r) : "f"(a), "f"(b)); return r;
}
__device__ __forceinline__ void unpack2(ull v, float& a, float& b) {
    asm("mov.b64 {%0, %1}, %2;" : "=f"(a), "=f"(b) : "l"(v));
}
// packed dual fp32 FMA (sm_100+; ptxas never auto-fuses this -> 2x fp32 FMA rate)
__device__ __forceinline__ ull ffma2(ull a, ull b, ull c) {
    ull d; asm("fma.rn.f32x2 %0, %1, %2, %3;" : "=l"(d) : "l"(a), "l"(b), "l"(c));
    return d;
}

// Accurate-enough activations built only from __expf + fast reciprocal
// (abs err ~1e-7; deliberately NOT tanhf, which --use_fast_math would turn
// into MUFU.TANH with ~1e-3 abs error -- too coarse for 256 recurrent steps).
__device__ __forceinline__ float fsig(float x) {
    return __fdividef(1.f, 1.f + __expf(-x));
}
__device__ __forceinline__ float ftanh(float x) {
    return __fdividef(2.f, 1.f + __expf(-2.f * x)) - 1.f;
}

template <int IN, bool IS_L1>
__global__ void __launch_bounds__(256, 1) lstm_kernel(
    const float* __restrict__ xin,   // L1: x [B,T,IN]; L2: unused (reads g_ys1)
    const float* __restrict__ w_ih,  // [4H, IN]
    const float* __restrict__ w_hh,  // [4H, H]
    const float* __restrict__ b_ih,  // [4H]
    const float* __restrict__ b_hh,  // [4H]
    const float* __restrict__ fc_w,  // [O, H]   (L2 only)
    const float* __restrict__ fc_b,  // [O]      (L2 only)
    float* __restrict__ out)         // [B, O]   (L2 only)
{
    constexpr int K = IN + H;        // fused input+recurrent contraction dim
    extern __shared__ float sm[];
    float* sW    = sm;               // [K][PJ]   weights, transposed (k-major)
    float* sXH   = sW + K * PJ;      // [K][BSP]  staged x_t rows + h rows
    float* sG    = sXH + K * BSP;    // [BS][PJ]  gate pre-activations
    float* sBias = sG + BS * PJ;     // [G4]      b_ih + b_hh

    const int tid = threadIdx.x;
    const int batch0 = blockIdx.x * BS;

    // ---- one-time: weights -> SMEM, transposed so gate index is contiguous
    for (int idx = tid; idx < G4 * IN; idx += 256) {
        int j = idx / IN, k = idx - j * IN;
        sW[k * PJ + j] = w_ih[idx];
    }
    for (int idx = tid; idx < G4 * H; idx += 256) {
        int j = idx >> 6, k = idx & 63;
        sW[(IN + k) * PJ + j] = w_hh[idx];
    }
    sBias[tid] = b_ih[tid] + b_hh[tid];
    for (int idx = tid; idx < H * BSP; idx += 256) sXH[IN * BSP + idx] = 0.f;  // h0 = 0
    __syncthreads();

    // Phase-B tile: 4 batch x 4 gates per thread (b0 = broadcast group)
    const int j0 = (tid & 63) << 2;
    const int b0 = (tid >> 6) << 2;
    // Phase-C ownership: one h index, 4 batch elements (c state lives in regs)
    const int hC = tid & 63;
    const int bC = (tid >> 6) << 2;

    const float4 bv = *(const float4*)(sBias + j0);
    const ull bias01 = pack2(bv.x, bv.y);
    const ull bias23 = pack2(bv.z, bv.w);

    float c_reg[4] = {0.f, 0.f, 0.f, 0.f};

    for (int t = 0; t < T; ++t) {
        // ---- Phase A: stage x_t (transposed to [k][b]) into sXH[0..IN)
        if constexpr (IS_L1) {
            for (int idx = tid; idx < BS * IN; idx += 256) {
                int b = idx / IN, k = idx - b * IN;
                sXH[k * BSP + b] = xin[((size_t)(batch0 + b) * T + t) * IN + k];
            }
        } else {
            for (int idx = tid; idx < BS * IN; idx += 256) {
                int b = idx / IN, k = idx - b * IN;
                sXH[k * BSP + b] = g_ys1[((size_t)t * B + (batch0 + b)) * H + k];
            }
        }
        __syncthreads();  // also orders prev-step h writes before this GEMM

        // ---- Phase B: gates[b][j] = sum_k xh[k][b] * W[k][j] + bias
        ull a00 = bias01, a01 = bias23, a10 = bias01, a11 = bias23;
        ull a20 = bias01, a21 = bias23, a30 = bias01, a31 = bias23;
        #pragma unroll 8
        for (int k = 0; k < K; ++k) {
            const float4 w  = *(const float4*)(sW  + k * PJ  + j0);  // per-thread
            const float4 xv = *(const float4*)(sXH + k * BSP + b0);  // warp-broadcast
            const ull w01 = pack2(w.x, w.y), w23 = pack2(w.z, w.w);
            ull xx;
            xx = pack2(xv.x, xv.x); a00 = ffma2(xx, w01, a00); a01 = ffma2(xx, w23, a01);
            xx = pack2(xv.y, xv.y); a10 = ffma2(xx, w01, a10); a11 = ffma2(xx, w23, a11);
            xx = pack2(xv.z, xv.z); a20 = ffma2(xx, w01, a20); a21 = ffma2(xx, w23, a21);
            xx = pack2(xv.w, xv.w); a30 = ffma2(xx, w01, a30); a31 = ffma2(xx, w23, a31);
        }
        {
            float4 r;
            unpack2(a00, r.x, r.y); unpack2(a01, r.z, r.w);
            *(float4*)(sG + (b0 + 0) * PJ + j0) = r;
            unpack2(a10, r.x, r.y); unpack2(a11, r.z, r.w);
            *(float4*)(sG + (b0 + 1) * PJ + j0) = r;
            unpack2(a20, r.x, r.y); unpack2(a21, r.z, r.w);
            *(float4*)(sG + (b0 + 2) * PJ + j0) = r;
            unpack2(a30, r.x, r.y); unpack2(a31, r.z, r.w);
            *(float4*)(sG + (b0 + 3) * PJ + j0) = r;
        }
        __syncthreads();

        // ---- Phase C: LSTM cell elementwise; h feeds back into sXH
        #pragma unroll
        for (int q = 0; q < 4; ++q) {
            const int b = bC + q;
            float gi = sG[b * PJ + hC];
            float gf = sG[b * PJ + 64 + hC];
            float gg = sG[b * PJ + 128 + hC];
            float go = sG[b * PJ + 192 + hC];
            gi = fsig(gi); gf = fsig(gf); go = fsig(go);
            gg = ftanh(gg);
            const float c = gf * c_reg[q] + gi * gg;
            c_reg[q] = c;
            const float hv = go * ftanh(c);
            sXH[(IN + hC) * BSP + b] = hv;
            if constexpr (IS_L1)
                g_ys1[((size_t)t * B + (batch0 + b)) * H + hC] = hv;
        }
        // barrier before next Phase B is the __syncthreads after next Phase A
    }

    // ---- layer2 epilogue: fused FC head out = h_last @ fc_w^T + fc_b
    if constexpr (!IS_L1) {
        __syncthreads();
        for (int idx = tid; idx < BS * O; idx += 256) {
            int b = idx / O, o = idx - (idx / O) * O;
            float s = fc_b[o];
            #pragma unroll
            for (int h = 0; h < H; ++h)
                s += sXH[(IN + h) * BSP + b] * fc_w[o * H + h];
            out[(batch0 + b) * O + o] = s;
        }
    }
}

extern "C" void kernel_launch(void* const* d_in, const int* in_sizes, int n_in,
                              void* d_out, int out_size) {
    const float* x     = (const float*)d_in[0];
    const float* w_ih0 = (const float*)d_in[1];
    const float* w_hh0 = (const float*)d_in[2];
    const float* b_ih0 = (const float*)d_in[3];
    const float* b_hh0 = (const float*)d_in[4];
    const float* w_ih1 = (const float*)d_in[5];
    const float* w_hh1 = (const float*)d_in[6];
    const float* b_ih1 = (const float*)d_in[7];
    const float* b_hh1 = (const float*)d_in[8];
    const float* fc_w  = (const float*)d_in[9];
    const float* fc_b  = (const float*)d_in[10];
    float* out = (float*)d_out;

    constexpr int K1 = I + H;   // 152
    constexpr int K2 = H + H;   // 128
    const size_t sm1 = (size_t)(K1 * PJ + K1 * BSP + BS * PJ + G4) * sizeof(float); // ~184 KB
    const size_t sm2 = (size_t)(K2 * PJ + K2 * BSP + BS * PJ + G4) * sizeof(float); // ~157 KB

    cudaFuncSetAttribute(lstm_kernel<I, true>,
                         cudaFuncAttributeMaxDynamicSharedMemorySize, (int)sm1);
    cudaFuncSetAttribute(lstm_kernel<H, false>,
                         cudaFuncAttributeMaxDynamicSharedMemorySize, (int)sm2);

    lstm_kernel<I, true><<<B / BS, 256, sm1>>>(
        x, w_ih0, w_hh0, b_ih0, b_hh0, nullptr, nullptr, nullptr);
    lstm_kernel<H, false><<<B / BS, 256, sm2>>>(
        nullptr, w_ih1, w_hh1, b_ih1, b_hh1, fc_w, fc_b, out);
}